// round 11
// baseline (speedup 1.0000x reference)
#include <cuda_runtime.h>
#include <cstdint>
#include <math.h>

#define BATCH 8
#define CIN   28
#define COUT  28
#define HH    256
#define WW    256
#define DGRP  7
#define KHT   7
#define CPG   4
#define HW    (HH*WW)

typedef unsigned long long ull;

__device__ __forceinline__ ull pk2(float a, float b) {
    ull r; asm("mov.b64 %0, {%1,%2};" : "=l"(r) : "f"(a), "f"(b)); return r;
}
__device__ __forceinline__ ull pk1(float a) { return pk2(a, a); }
__device__ __forceinline__ void upk(ull v, float& a, float& b) {
    asm("mov.b64 {%0,%1}, %2;" : "=f"(a), "=f"(b) : "l"(v));
}
__device__ __forceinline__ ull f2fma(ull a, ull b, ull c) {
    ull d; asm("fma.rn.f32x2 %0, %1, %2, %3;" : "=l"(d) : "l"(a), "l"(b), "l"(c)); return d;
}
__device__ __forceinline__ ull f2mul(ull a, ull b) {
    ull d; asm("mul.rn.f32x2 %0, %1, %2;" : "=l"(d) : "l"(a), "l"(b)); return d;
}

// ---- precomputed weights ----
__device__ float g_W1F[DGRP * KHT * CPG * COUT];   // [tap][c][o]  natural floats (pairs over o)
__device__ float g_W2F[COUT * 7 * 4 * 8];          // [o2][kw][ohq][8] floats (7 used)
__device__ float g_b2[COUT];

__global__ void prep_kernel(const float* __restrict__ weight, const float* __restrict__ w_t,
                            const float* __restrict__ b_t, const float* __restrict__ w_m,
                            const float* __restrict__ b_m) {
    int gid = blockIdx.x * blockDim.x + threadIdx.x;
    int nth = gridDim.x * blockDim.x;

    // W1F: [(tap*4+c)*28 + o] = weight[o][g*4+c][i]
    for (int e = gid; e < 5488; e += nth) {
        int o = e % 28; int r = e / 28;
        int c = r & 3; int tap = r >> 2;
        int g = tap / 7, i = tap % 7;
        g_W1F[e] = weight[(o * CIN + (g * CPG + c)) * KHT + i];
    }

    // W2F (stage-3 folded): offset = ((o2*7+kw)*4+ohq)*8 + j ; channel = ohq*7+j
    for (int e = gid; e < 6272; e += nth) {
        int j = e & 7; int q = e >> 3;
        int ohq = q & 3; q >>= 2;
        int kw = q % 7; int o2 = q / 7;
        float v = 0.f;
        if (j < 7) {
            int oc = ohq * 7 + j;
            int f = oc >> 2, cc = oc & 3;
#pragma unroll
            for (int g = 0; g < DGRP; g++)
                v += w_m[f * DGRP + g] * w_t[((g * CPG + cc) * COUT + o2) * 7 + kw];
        }
        g_W2F[e] = v;
    }

    if (gid < COUT) {
        int f = gid >> 2, cc = gid & 3;
        float s = 0.f;
#pragma unroll
        for (int g = 0; g < DGRP; g++) s += w_m[f * DGRP + g] * b_t[g * CPG + cc];
        g_b2[gid] = s + b_m[f];
    }
}

// ---- fused kernel smem layout (bytes) ----
constexpr int F_W1   = 0;                        // float[5488] 21952
constexpr int F_W2   = 21952;                    // float[6272] 25088
constexpr int F_B1   = 47040;                    // float[32]
constexpr int F_B2   = 47168;                    // float[32]
constexpr int F_TL0  = 47296;                    // ull[64]
constexpr int F_TL1  = 47808;                    // ull[64]
constexpr int F_TY0  = 48320;                    // int[64] (premult by WW)
constexpr int F_TY1  = 48576;                    // int[64]
constexpr int F_R    = 48832;                    // float[28*264] 29568
constexpr int F_SMEM = F_R + 29568;              // 78400 (~76.6KB) -> 2 CTAs/SM

__global__ void __launch_bounds__(256, 2)
fused_kernel(const float* __restrict__ x, const float* __restrict__ bias1,
             float* __restrict__ out) {
    extern __shared__ char sm[];
    float* W1f = (float*)(sm + F_W1);
    float* W2f = (float*)(sm + F_W2);
    float* b1s = (float*)(sm + F_B1);
    float* b2s = (float*)(sm + F_B2);
    ull*   tl0 = (ull*)(sm + F_TL0);
    ull*   tl1 = (ull*)(sm + F_TL1);
    int*   ty0 = (int*)(sm + F_TY0);
    int*   ty1 = (int*)(sm + F_TY1);
    float* R   = (float*)(sm + F_R);

    const int tid = threadIdx.x;
    const int h = blockIdx.x;
    const int b = blockIdx.y;

    for (int i = tid; i < 5488; i += 256) W1f[i] = g_W1F[i];
    for (int i = tid; i < 6272; i += 256) W2f[i] = g_W2F[i];
    if (tid < 28) { b1s[tid] = bias1[tid]; b2s[tid] = g_b2[tid]; }

    if (tid < 49) {
        int g = tid / 7, i = tid % 7;
        double yp = (double)((h + 1) * (i + 1)) / (double)(g + 1) - 4.0;
        double y0 = floor(yp);
        float fy = (float)(yp - y0);
        int y0i = (int)y0;
        bool v0 = (y0i >= 0) && (y0i <= HH - 1);
        bool v1 = (y0i + 1 >= 0) && (y0i + 1 <= HH - 1);
        int ya = y0i < 0 ? 0 : (y0i > HH - 1 ? HH - 1 : y0i);
        int yb = (y0i + 1) < 0 ? 0 : (y0i + 1 > HH - 1 ? HH - 1 : y0i + 1);
        ty0[tid] = ya * WW;
        ty1[tid] = yb * WW;
        tl0[tid] = v0 ? pk1(1.0f - fy) : 0ull;
        tl1[tid] = v1 ? pk1(fy) : 0ull;
    }

    // R halos
    if (tid < 28) {
        float* Rr = R + tid * 264;
        Rr[0] = Rr[1] = Rr[2] = Rr[3] = 0.f;
        Rr[260] = Rr[261] = Rr[262] = Rr[263] = 0.f;
    }
    __syncthreads();

    // ========== Phase A: harmonic sample + 1st contraction ==========
    // acc[jp][wc]: channel-pair (ohh*14+2jp, +1) at w-col (2p + wc).
    // Weights are natural float pairs via broadcast LDS.64 (no splat).
    {
        const int p = tid & 127;
        const int ohh = tid >> 7;
        const int wb = 2 * p;

        ull acc[7][2];
#pragma unroll
        for (int jp = 0; jp < 7; jp++) {
            ull bv = *(const ull*)(b1s + ohh * 14 + 2 * jp);
            acc[jp][0] = bv; acc[jp][1] = bv;
        }

        const float* rbg = x + (size_t)b * CIN * HW + wb;

#pragma unroll 1
        for (int g = 0; g < 7; g++, rbg += (size_t)CPG * HW) {
#pragma unroll 1
            for (int i = 0; i < 7; i++) {
                const int tap = g * 7 + i;
                const ull lw0 = tl0[tap], lw1 = tl1[tap];
                if ((lw0 | lw1) == 0ull) continue;   // uniform across CTA
                const int y0 = ty0[tap], y1 = ty1[tap];
#pragma unroll
                for (int c = 0; c < 4; c++) {
                    ull xv0 = *(const ull*)(rbg + (size_t)c * HW + y0);
                    ull xv1 = *(const ull*)(rbg + (size_t)c * HW + y1);
                    ull s2 = f2fma(lw1, xv1, f2mul(lw0, xv0));
                    float sa, sb; upk(s2, sa, sb);
                    ull sA = pk1(sa), sB = pk1(sb);
                    const ull* wp = (const ull*)(W1f + (tap * 4 + c) * 28 + ohh * 14);
#pragma unroll
                    for (int jp = 0; jp < 7; jp++) {
                        ull w = wp[jp];
                        acc[jp][0] = f2fma(w, sA, acc[jp][0]);
                        acc[jp][1] = f2fma(w, sB, acc[jp][1]);
                    }
                }
            }
        }

        // write 2x2 blocks into R (interior offset +4)
#pragma unroll
        for (int jp = 0; jp < 7; jp++) {
            int e = ohh * 14 + 2 * jp;
            float a0, a1, c0, c1;
            upk(acc[jp][0], a0, a1);   // (ch e @ wb, ch e+1 @ wb)
            upk(acc[jp][1], c0, c1);   // (ch e @ wb+1, ch e+1 @ wb+1)
            *(ull*)(R + e * 264 + 4 + wb)       = pk2(a0, c0);
            *(ull*)(R + (e + 1) * 264 + 4 + wb) = pk2(a1, c1);
        }
    }
    __syncthreads();

    // ========== Phase B: 1x7 conv along W (+ stage-3 folded) ==========
    {
        const int p2 = tid & 63;
        const int ohq = tid >> 6;
        const int base = 4 * p2;

        ull a2[7][2];
#pragma unroll
        for (int o = 0; o < 7; o++) { ull bv = pk1(b2s[ohq * 7 + o]); a2[o][0] = bv; a2[o][1] = bv; }

#pragma unroll 1
        for (int o2 = 0; o2 < 28; o2++) {
            const float4* Rw = (const float4*)(R + o2 * 264 + base);
            float r[12];
            *(float4*)(r)     = Rw[0];
            *(float4*)(r + 4) = Rw[1];
            *(float4*)(r + 8) = Rw[2];
            const float* wbp = W2f + (((o2 * 7) * 4 + ohq) << 3);
#pragma unroll
            for (int kw = 0; kw < 7; kw++) {
                ull vA = pk2(r[kw + 1], r[kw + 2]);
                ull vB = pk2(r[kw + 3], r[kw + 4]);
                float4 wa = *(const float4*)(wbp + kw * 32);
                float4 wc = *(const float4*)(wbp + kw * 32 + 4);
                ull W0 = pk1(wa.x), W1 = pk1(wa.y), W2 = pk1(wa.z), W3 = pk1(wa.w);
                ull W4 = pk1(wc.x), W5 = pk1(wc.y), W6 = pk1(wc.z);
                a2[0][0] = f2fma(W0, vA, a2[0][0]); a2[0][1] = f2fma(W0, vB, a2[0][1]);
                a2[1][0] = f2fma(W1, vA, a2[1][0]); a2[1][1] = f2fma(W1, vB, a2[1][1]);
                a2[2][0] = f2fma(W2, vA, a2[2][0]); a2[2][1] = f2fma(W2, vB, a2[2][1]);
                a2[3][0] = f2fma(W3, vA, a2[3][0]); a2[3][1] = f2fma(W3, vB, a2[3][1]);
                a2[4][0] = f2fma(W4, vA, a2[4][0]); a2[4][1] = f2fma(W4, vB, a2[4][1]);
                a2[5][0] = f2fma(W5, vA, a2[5][0]); a2[5][1] = f2fma(W5, vB, a2[5][1]);
                a2[6][0] = f2fma(W6, vA, a2[6][0]); a2[6][1] = f2fma(W6, vB, a2[6][1]);
            }
        }

        float* ob = out + (((size_t)b * COUT + ohq * 7) * HH + h) * WW + base;
#pragma unroll
        for (int o = 0; o < 7; o++) {
            ulonglong2 v; v.x = a2[o][0]; v.y = a2[o][1];
            *(ulonglong2*)(ob + (size_t)o * HW) = v;
        }
    }
}

extern "C" void kernel_launch(void* const* d_in, const int* in_sizes, int n_in,
                              void* d_out, int out_size) {
    const float* x      = (const float*)d_in[0];
    const float* weight = (const float*)d_in[1];
    const float* bias   = (const float*)d_in[2];
    const float* w_t    = (const float*)d_in[3];
    const float* b_t    = (const float*)d_in[4];
    const float* w_m    = (const float*)d_in[5];
    const float* b_m    = (const float*)d_in[6];
    float* out = (float*)d_out;

    cudaFuncSetAttribute(fused_kernel, cudaFuncAttributeMaxDynamicSharedMemorySize, F_SMEM);

    prep_kernel<<<32, 256>>>(weight, w_t, b_t, w_m, b_m);
    fused_kernel<<<dim3(HH, BATCH), 256, F_SMEM>>>(x, bias, out);
}

// round 12
// speedup vs baseline: 1.5649x; 1.5649x over previous
#include <cuda_runtime.h>
#include <cstdint>
#include <math.h>

#define BATCH 8
#define CIN   28
#define COUT  28
#define HH    256
#define WW    256
#define DGRP  7
#define KHT   7
#define CPG   4
#define HW    (HH*WW)

typedef unsigned long long ull;

__device__ __forceinline__ ull pk2(float a, float b) {
    ull r; asm("mov.b64 %0, {%1,%2};" : "=l"(r) : "f"(a), "f"(b)); return r;
}
__device__ __forceinline__ ull pk1(float a) { return pk2(a, a); }
__device__ __forceinline__ ull f2fma(ull a, ull b, ull c) {
    ull d; asm("fma.rn.f32x2 %0, %1, %2, %3;" : "=l"(d) : "l"(a), "l"(b), "l"(c)); return d;
}
__device__ __forceinline__ ull f2mul(ull a, ull b) {
    ull d; asm("mul.rn.f32x2 %0, %1, %2;" : "=l"(d) : "l"(a), "l"(b)); return d;
}
__device__ __forceinline__ void cp16(void* dst, const void* src) {
    unsigned s = (unsigned)__cvta_generic_to_shared(dst);
    asm volatile("cp.async.cg.shared.global [%0], [%1], 16;" :: "r"(s), "l"(src));
}
__device__ __forceinline__ ull splat_dev(float v) {
    unsigned u = __float_as_uint(v); return ((ull)u << 32) | (ull)u;
}

// ---- global scratch ----
__device__ float g_mid[(size_t)BATCH * COUT * HH * WW];   // 58.7MB stage-1 output
__device__ ull   g_W1P[2 * DGRP * KHT * CPG * 2 * 7];     // [tap][c][ohh][j] -> ull2 pair
__device__ ull   g_W2P[2 * COUT * 7 * 4 * 4];             // [o2][kw][ohq][j] -> ull2 pair (ch pad)
__device__ float g_b2[COUT];

__global__ void prep_kernel(const float* __restrict__ weight, const float* __restrict__ w_t,
                            const float* __restrict__ b_t, const float* __restrict__ w_m,
                            const float* __restrict__ b_m) {
    int gid = blockIdx.x * blockDim.x + threadIdx.x;
    int nth = gridDim.x * blockDim.x;

    for (int e = gid; e < 2744; e += nth) {
        int j = e % 7; int r = e / 7;
        int ohh = r & 1; r >>= 1;
        int c = r & 3; int tap = r >> 2;
        int g = tap / 7, i = tap % 7;
        int o0 = ohh * 14 + 2 * j;
        float wa = weight[(o0 * CIN + (g * CPG + c)) * KHT + i];
        float wb = weight[((o0 + 1) * CIN + (g * CPG + c)) * KHT + i];
        g_W1P[2 * e]     = splat_dev(wa);
        g_W1P[2 * e + 1] = splat_dev(wb);
    }

    for (int e2 = gid; e2 < 3136; e2 += nth) {
        int j = e2 & 3; int q = e2 >> 2;
        int ohq = q & 3; q >>= 2;
        int kw = q % 7; int o2 = q / 7;
        float va = 0.f, vb = 0.f;
        int oc0 = ohq * 7 + 2 * j;
        {
            int f = oc0 >> 2, cc = oc0 & 3;
#pragma unroll
            for (int g = 0; g < DGRP; g++)
                va += w_m[f * DGRP + g] * w_t[((g * CPG + cc) * COUT + o2) * 7 + kw];
        }
        if (2 * j + 1 < 7) {
            int oc1 = oc0 + 1;
            int f = oc1 >> 2, cc = oc1 & 3;
#pragma unroll
            for (int g = 0; g < DGRP; g++)
                vb += w_m[f * DGRP + g] * w_t[((g * CPG + cc) * COUT + o2) * 7 + kw];
        }
        g_W2P[2 * e2]     = splat_dev(va);
        g_W2P[2 * e2 + 1] = splat_dev(vb);
    }

    if (gid < COUT) {
        int f = gid >> 2, cc = gid & 3;
        float s = 0.f;
#pragma unroll
        for (int g = 0; g < DGRP; g++) s += w_m[f * DGRP + g] * b_t[g * CPG + cc];
        g_b2[gid] = s + b_m[f];
    }
}

// =========================== Stage 1 (identical to R3 best) ==================
constexpr int A_W1   = 0;                        // ull[5488] 43904
constexpr int A_B1   = 43904;                    // float[32]
constexpr int A_MT   = 44032;                    // int[128] tap
constexpr int A_MG   = A_MT + 512;               // int[128] g
constexpr int A_MY0  = A_MG + 512;
constexpr int A_MY1  = A_MY0 + 512;
constexpr int A_MW0  = A_MY1 + 512;              // ull[128]
constexpr int A_MW1  = A_MW0 + 1024;
constexpr int A_MNL  = A_MW1 + 1024;             // int[4]
constexpr int A_TL0  = A_MNL + 16;               // ull[128]
constexpr int A_TL1  = A_TL0 + 1024;
constexpr int A_TY0  = A_TL1 + 1024;             // int[128]
constexpr int A_TY1  = A_TY0 + 512;
constexpr int A_SMEM = A_TY1 + 512;              // ~51.7KB

__global__ void __launch_bounds__(256, 2)
stage1_kernel(const float* __restrict__ x, const float* __restrict__ bias1) {
    extern __shared__ char sm[];
    ull*   W1p  = (ull*)(sm + A_W1);
    float* b1s  = (float*)(sm + A_B1);
    int*   mTap = (int*)(sm + A_MT);
    int*   mG   = (int*)(sm + A_MG);
    int*   mY0  = (int*)(sm + A_MY0);
    int*   mY1  = (int*)(sm + A_MY1);
    ull*   mW0  = (ull*)(sm + A_MW0);
    ull*   mW1  = (ull*)(sm + A_MW1);
    int*   mNL  = (int*)(sm + A_MNL);
    ull*   tl0  = (ull*)(sm + A_TL0);
    ull*   tl1  = (ull*)(sm + A_TL1);
    int*   ty0  = (int*)(sm + A_TY0);
    int*   ty1  = (int*)(sm + A_TY1);

    const int tid = threadIdx.x;
    const int hz  = tid >> 7;
    const int t   = tid & 127;
    const int h   = blockIdx.x * 2 + hz;
    const int b   = blockIdx.y;

    for (int i = tid; i < 5488; i += 256) W1p[i] = g_W1P[i];
    if (tid < 28) b1s[tid] = bias1[tid];

    if (t < 49) {
        int g = t / 7, i = t % 7;
        double yp = (double)((h + 1) * (i + 1)) / (double)(g + 1) - 4.0;
        double y0 = floor(yp);
        float fy = (float)(yp - y0);
        int y0i = (int)y0;
        bool v0 = (y0i >= 0) && (y0i <= HH - 1);
        bool v1 = (y0i + 1 >= 0) && (y0i + 1 <= HH - 1);
        ty0[hz * 64 + t] = y0i < 0 ? 0 : (y0i > HH - 1 ? HH - 1 : y0i);
        ty1[hz * 64 + t] = (y0i + 1) < 0 ? 0 : (y0i + 1 > HH - 1 ? HH - 1 : y0i + 1);
        tl0[hz * 64 + t] = v0 ? pk1(1.0f - fy) : 0ull;
        tl1[hz * 64 + t] = v1 ? pk1(fy) : 0ull;
    }
    __syncthreads();
    if (t == 0) {
        int n = 0;
        for (int k = 0; k < 49; k++) {
            if ((tl0[hz * 64 + k] | tl1[hz * 64 + k]) != 0ull) {
                mTap[hz * 64 + n] = k;
                mG[hz * 64 + n]   = k / 7;
                mY0[hz * 64 + n]  = ty0[hz * 64 + k];
                mY1[hz * 64 + n]  = ty1[hz * 64 + k];
                mW0[hz * 64 + n]  = tl0[hz * 64 + k];
                mW1[hz * 64 + n]  = tl1[hz * 64 + k];
                n++;
            }
        }
        mNL[hz] = n;
    }
    __syncthreads();

    const int p = t & 63;
    const int ohh = t >> 6;
    const int wbase = 4 * p;

    ull acc[14][2];
#pragma unroll
    for (int o = 0; o < 14; o++) { ull bv = pk1(b1s[ohh * 14 + o]); acc[o][0] = bv; acc[o][1] = bv; }

    const float* xb = x + (size_t)b * CIN * HW + wbase;
    const int nl = mNL[hz];
    const int mbase = hz * 64;

#pragma unroll 1
    for (int tt = 0; tt < nl; tt++) {
        const int tap = mTap[mbase + tt];
        const int g   = mG[mbase + tt];
        const int y0  = mY0[mbase + tt];
        const int y1  = mY1[mbase + tt];
        const ull lw0 = mW0[mbase + tt];
        const ull lw1 = mW1[mbase + tt];
        const float* rb = xb + (size_t)g * CPG * HW;
        ull s[4][2];
#pragma unroll
        for (int c = 0; c < 4; c++) {
            const ulonglong2 xv0 = *(const ulonglong2*)(rb + (size_t)c * HW + y0 * WW);
            const ulonglong2 xv1 = *(const ulonglong2*)(rb + (size_t)c * HW + y1 * WW);
            s[c][0] = f2fma(lw1, xv1.x, f2mul(lw0, xv0.x));
            s[c][1] = f2fma(lw1, xv1.y, f2mul(lw0, xv0.y));
        }
#pragma unroll
        for (int c = 0; c < 4; c++) {
            const ulonglong2* wc = (const ulonglong2*)W1p + ((tap * 4 + c) * 2 + ohh) * 7;
#pragma unroll
            for (int j = 0; j < 7; j++) {
                ulonglong2 w = wc[j];
                acc[2 * j][0]     = f2fma(w.x, s[c][0], acc[2 * j][0]);
                acc[2 * j][1]     = f2fma(w.x, s[c][1], acc[2 * j][1]);
                acc[2 * j + 1][0] = f2fma(w.y, s[c][0], acc[2 * j + 1][0]);
                acc[2 * j + 1][1] = f2fma(w.y, s[c][1], acc[2 * j + 1][1]);
            }
        }
    }

    float* mb = g_mid + (((size_t)b * COUT + ohh * 14) * HH + h) * WW + wbase;
#pragma unroll
    for (int o = 0; o < 14; o++) {
        ulonglong2 v; v.x = acc[o][0]; v.y = acc[o][1];
        *(ulonglong2*)(mb + (size_t)o * HW) = v;
    }
}

// ============== Stage 2 (+3 folded): 2 h-rows per CTA, weights amortized =====
constexpr int B_W2   = 0;                        // ull[6272] 50176
constexpr int B_B2   = 50176;                    // float[32] 128
constexpr int B_R    = 50304;                    // float[2*28*264] 59136
constexpr int B_ROWS = 7392;                     // floats per h-row block (28*264)
constexpr int B_SMEM = B_R + 59136;              // 109440 (~106.9KB) -> 2 CTAs/SM

__global__ void __launch_bounds__(256, 2)
stage2_kernel(float* __restrict__ out) {
    extern __shared__ char sm[];
    ull*   W2p = (ull*)(sm + B_W2);
    float* b2s = (float*)(sm + B_B2);
    float* R   = (float*)(sm + B_R);

    const int tid = threadIdx.x;
    const int h0 = blockIdx.x * 2;
    const int b = blockIdx.y;

    // stage mid rows for both h into R blocks (interior offset +4)
#pragma unroll
    for (int hz = 0; hz < 2; hz++) {
        const float* mrow = g_mid + ((size_t)b * COUT * HH + (h0 + hz)) * WW;
#pragma unroll
        for (int k = 0; k < 7; k++) {
            int idx = tid + 256 * k;
            int row = idx >> 6;
            int ch  = idx & 63;
            cp16(R + hz * B_ROWS + row * 264 + 4 + ch * 4, mrow + (size_t)row * HW + ch * 4);
        }
    }
    asm volatile("cp.async.commit_group;" ::: "memory");

    for (int i = tid; i < 6272; i += 256) W2p[i] = g_W2P[i];
    if (tid < 28) b2s[tid] = g_b2[tid];
    if (tid < 56) {
        int hz = tid / 28, row = tid % 28;
        float* Rr = R + hz * B_ROWS + row * 264;
        Rr[0] = Rr[1] = Rr[2] = Rr[3] = 0.f;
        Rr[260] = Rr[261] = Rr[262] = Rr[263] = 0.f;
    }
    asm volatile("cp.async.wait_group 0;" ::: "memory");
    __syncthreads();

    const int p = tid & 63;
    const int ohq = tid >> 6;
    const int base = 4 * p;

    ull acc[2][7][2];
#pragma unroll
    for (int o = 0; o < 7; o++) {
        ull bv = pk1(b2s[ohq * 7 + o]);
        acc[0][o][0] = bv; acc[0][o][1] = bv;
        acc[1][o][0] = bv; acc[1][o][1] = bv;
    }

#pragma unroll 1
    for (int o2 = 0; o2 < 28; o2++) {
        float r0[12], r1[12];
        {
            const float4* Rw0 = (const float4*)(R + o2 * 264 + base);
            *(float4*)(r0)     = Rw0[0];
            *(float4*)(r0 + 4) = Rw0[1];
            *(float4*)(r0 + 8) = Rw0[2];
            const float4* Rw1 = (const float4*)(R + B_ROWS + o2 * 264 + base);
            *(float4*)(r1)     = Rw1[0];
            *(float4*)(r1 + 4) = Rw1[1];
            *(float4*)(r1 + 8) = Rw1[2];
        }
#pragma unroll
        for (int kw = 0; kw < 7; kw++) {
            const ulonglong2* wq = (const ulonglong2*)W2p + (((o2 * 7 + kw) * 4 + ohq) << 2);
            ulonglong2 w0 = wq[0], w1 = wq[1], w2 = wq[2], w3 = wq[3];
            {
                ull vA = pk2(r0[kw + 1], r0[kw + 2]);
                ull vB = pk2(r0[kw + 3], r0[kw + 4]);
                acc[0][0][0] = f2fma(w0.x, vA, acc[0][0][0]); acc[0][0][1] = f2fma(w0.x, vB, acc[0][0][1]);
                acc[0][1][0] = f2fma(w0.y, vA, acc[0][1][0]); acc[0][1][1] = f2fma(w0.y, vB, acc[0][1][1]);
                acc[0][2][0] = f2fma(w1.x, vA, acc[0][2][0]); acc[0][2][1] = f2fma(w1.x, vB, acc[0][2][1]);
                acc[0][3][0] = f2fma(w1.y, vA, acc[0][3][0]); acc[0][3][1] = f2fma(w1.y, vB, acc[0][3][1]);
                acc[0][4][0] = f2fma(w2.x, vA, acc[0][4][0]); acc[0][4][1] = f2fma(w2.x, vB, acc[0][4][1]);
                acc[0][5][0] = f2fma(w2.y, vA, acc[0][5][0]); acc[0][5][1] = f2fma(w2.y, vB, acc[0][5][1]);
                acc[0][6][0] = f2fma(w3.x, vA, acc[0][6][0]); acc[0][6][1] = f2fma(w3.x, vB, acc[0][6][1]);
            }
            {
                ull vA = pk2(r1[kw + 1], r1[kw + 2]);
                ull vB = pk2(r1[kw + 3], r1[kw + 4]);
                acc[1][0][0] = f2fma(w0.x, vA, acc[1][0][0]); acc[1][0][1] = f2fma(w0.x, vB, acc[1][0][1]);
                acc[1][1][0] = f2fma(w0.y, vA, acc[1][1][0]); acc[1][1][1] = f2fma(w0.y, vB, acc[1][1][1]);
                acc[1][2][0] = f2fma(w1.x, vA, acc[1][2][0]); acc[1][2][1] = f2fma(w1.x, vB, acc[1][2][1]);
                acc[1][3][0] = f2fma(w1.y, vA, acc[1][3][0]); acc[1][3][1] = f2fma(w1.y, vB, acc[1][3][1]);
                acc[1][4][0] = f2fma(w2.x, vA, acc[1][4][0]); acc[1][4][1] = f2fma(w2.x, vB, acc[1][4][1]);
                acc[1][5][0] = f2fma(w2.y, vA, acc[1][5][0]); acc[1][5][1] = f2fma(w2.y, vB, acc[1][5][1]);
                acc[1][6][0] = f2fma(w3.x, vA, acc[1][6][0]); acc[1][6][1] = f2fma(w3.x, vB, acc[1][6][1]);
            }
        }
    }

#pragma unroll
    for (int hz = 0; hz < 2; hz++) {
        float* ob = out + (((size_t)b * COUT + ohq * 7) * HH + (h0 + hz)) * WW + base;
#pragma unroll
        for (int o = 0; o < 7; o++) {
            ulonglong2 v; v.x = acc[hz][o][0]; v.y = acc[hz][o][1];
            *(ulonglong2*)(ob + (size_t)o * HW) = v;
        }
    }
}

extern "C" void kernel_launch(void* const* d_in, const int* in_sizes, int n_in,
                              void* d_out, int out_size) {
    const float* x      = (const float*)d_in[0];
    const float* weight = (const float*)d_in[1];
    const float* bias   = (const float*)d_in[2];
    const float* w_t    = (const float*)d_in[3];
    const float* b_t    = (const float*)d_in[4];
    const float* w_m    = (const float*)d_in[5];
    const float* b_m    = (const float*)d_in[6];
    float* out = (float*)d_out;

    cudaFuncSetAttribute(stage1_kernel, cudaFuncAttributeMaxDynamicSharedMemorySize, A_SMEM);
    cudaFuncSetAttribute(stage2_kernel, cudaFuncAttributeMaxDynamicSharedMemorySize, B_SMEM);

    prep_kernel<<<32, 256>>>(weight, w_t, b_t, w_m, b_m);
    stage1_kernel<<<dim3(HH / 2, BATCH), 256, A_SMEM>>>(x, bias);
    stage2_kernel<<<dim3(HH / 2, BATCH), 256, B_SMEM>>>(out);
}